// round 14
// baseline (speedup 1.0000x reference)
#include <cuda_runtime.h>
#include <cuda_bf16.h>

// ParametricInterpolation, round 12: 4 outputs per thread (ILP on the
// data-dependent gather round-trip), float4 stores, 32-CTA grid.
//
// PROTECTED NUMERICS (R6/R10 pass, rel_err 7.7e-8 — rint-critical per i):
//   p_k = rn( pb[k] * rn(1/scaler_k) )     (XLA divide-by-constant rewrite)
//   t2 = rn(t*t); t3 = rn(t2*t); t4 = rn(t2*t2)
//   cv = fmaf(p0,t4,0) -> fmaf(p1,t3,.) -> fmaf(p2,t2,.) -> fmaf(p3,t,.) -> +p4
//   ci = rintf(cv);  d = cv - ci (exact);  raw_pos = t - ci (exact int)
//   gather: weights {e^-16,e^-1,1,e^-1,e^-16}, ascending-j partials;
//   interior fast path multiplies by the constant reciprocal of the
//   constant-folded ascending weight sum (<=2ulp, tolerance 1e-3).

#ifndef SIG_LEN
#define SIG_LEN 2048
#endif

__device__ __forceinline__ void compute_one(
    int i, float p0, float p1, float p2, float p3, float p4,
    const float* __restrict__ xr,
    float& o_val, float& cv_out)
{
    const int N = SIG_LEN;

    float t  = (float)i;
    float t2 = __fmul_rn(t, t);
    float t3 = __fmul_rn(t2, t);
    float t4 = __fmul_rn(t2, t2);

    float cv = fmaf(p0, t4, 0.0f);
    cv = fmaf(p1, t3, cv);
    cv = fmaf(p2, t2, cv);
    cv = fmaf(p3, t,  cv);
    cv = __fadd_rn(cv, p4);

    float ci = rintf(cv);
    float d  = __fadd_rn(cv, -ci);

    float raw_pos = __fadd_rn(t, -ci);         // exact integer
    float np_f = fminf(fmaxf(raw_pos, 1.0f), 2047.0f);
    int m = (int)np_f;

    const float W1 = 0.36787944117144233f;     // f32(exp(-1))
    const float W2 = 1.1253517471925912e-07f;  // f32(exp(-16))
    const float WS = __fadd_rn(__fadd_rn(__fadd_rn(__fadd_rn(W2, W1), 1.0f), W1), W2);
    const float RW = __fdiv_rn(1.0f, WS);

    float a1, a2;
    if (m >= 3 && m <= 2044) {
        float xm3 = __ldg(xr + m - 3);
        float xm2 = __ldg(xr + m - 2);
        float xm1 = __ldg(xr + m - 1);
        float x0  = __ldg(xr + m);
        float xp1 = __ldg(xr + m + 1);
        float xp2 = __ldg(xr + m + 2);

        float s1 = __fmul_rn(xm2, W2);          // ascending j
        s1 = fmaf(xm1, W1, s1);
        s1 = __fadd_rn(s1, x0);
        s1 = fmaf(xp1, W1, s1);
        s1 = fmaf(xp2, W2, s1);

        float s2 = __fmul_rn(xm3, W2);
        s2 = fmaf(xm2, W1, s2);
        s2 = __fadd_rn(s2, xm1);
        s2 = fmaf(x0,  W1, s2);
        s2 = fmaf(xp1, W2, s2);

        a1 = __fmul_rn(s1, RW);
        a2 = __fmul_rn(s2, RW);
    } else {
        float s1 = 0.0f, w1s = 0.0f, s2 = 0.0f, w2s = 0.0f;
        #pragma unroll
        for (int o = -3; o <= 2; o++) {
            int j = m + o;
            if (j < 0 || j >= N) continue;
            float xv = __ldg(xr + j);
            float wk1 = (o == 0) ? 1.0f
                      : (o == -1 || o == 1) ? W1
                      : (o == -2 || o == 2) ? W2 : 0.0f;
            int o2 = o + 1;
            float wk2 = (o2 == 0) ? 1.0f
                      : (o2 == -1 || o2 == 1) ? W1
                      : (o2 == -2 || o2 == 2) ? W2 : 0.0f;
            s1  = fmaf(xv, wk1, s1);
            w1s = __fadd_rn(w1s, wk1);
            s2  = fmaf(xv, wk2, s2);
            w2s = __fadd_rn(w2s, wk2);
        }
        a1 = __fdiv_rn(s1, w1s);
        a2 = __fdiv_rn(s2, w2s);
    }

    float one_md = __fadd_rn(1.0f, -d);
    o_val = __fadd_rn(__fmul_rn(a1, one_md), __fmul_rn(a2, d));
    cv_out = cv;
}

__global__ __launch_bounds__(256)
void ParametricInterpolation_kernel(
    const float* __restrict__ x,       // [B, N]
    const float* __restrict__ params,  // [B, 5]
    float* __restrict__ out,           // [B, N]
    float* __restrict__ curve,         // [B, N] or nullptr
    int B)
{
    const int N = SIG_LEN;
    int tix = blockIdx.x * blockDim.x + threadIdx.x;   // 8192 threads
    int base = tix * 4;                                 // 4 outputs/thread
    if (base >= B * N) return;
    int b = base >> 11;           // all 4 indices share the row (4 | 2048)
    int i0 = base & (N - 1);

    // Params once per thread (amortized over 4 outputs).
    const float r0 = __fdiv_rn(1.0f, 1e11f);
    const float r1 = __fdiv_rn(1.0f, 1e7f);
    const float r2 = __fdiv_rn(1.0f, 1e3f);

    const float* pb = params + b * 5;
    float p0 = __fmul_rn(__ldg(pb + 0), r0);
    float p1 = __fmul_rn(__ldg(pb + 1), r1);
    float p2 = __fmul_rn(__ldg(pb + 2), r2);
    float p3 = __ldg(pb + 3);
    float p4 = __ldg(pb + 4);

    const float* xr = x + b * N;

    float ov[4], cvv[4];
    #pragma unroll
    for (int u = 0; u < 4; u++) {
        compute_one(i0 + u, p0, p1, p2, p3, p4, xr, ov[u], cvv[u]);
    }

    // Vector stores.
    float4 o4 = make_float4(ov[0], ov[1], ov[2], ov[3]);
    *reinterpret_cast<float4*>(out + base) = o4;
    if (curve) {
        float4 c4 = make_float4(cvv[0], cvv[1], cvv[2], cvv[3]);
        *reinterpret_cast<float4*>(curve + base) = c4;
    }
}

extern "C" void kernel_launch(void* const* d_in, const int* in_sizes, int n_in,
                              void* d_out, int out_size)
{
    const float* x      = (const float*)d_in[0];   // [B, 2048] f32
    const float* params = (const float*)d_in[1];   // [B, 5]    f32
    float* out = (float*)d_out;

    int B = in_sizes[1] / 5;           // 16
    int total = B * SIG_LEN;           // 32768

    float* curve = (out_size >= 2 * total) ? (out + total) : nullptr;

    int threads = 256;
    int blocks = (total / 4 + threads - 1) / threads;  // 32
    ParametricInterpolation_kernel<<<blocks, threads>>>(x, params, out, curve, B);
}

// round 16
// speedup vs baseline: 1.0746x; 1.0746x over previous
#include <cuda_runtime.h>
#include <cuda_bf16.h>

// ParametricInterpolation, round 14: converge on the measured-best shape
// (128 CTAs x 256 threads, 1 output/thread, interior fast path, no smem).
//
// PROTECTED NUMERICS (rel_err 7.7e-8, validated R7/R10/R12 benches):
//   p_k = rn( pb[k] * rn(1/scaler_k) )     (XLA divide-by-constant rewrite)
//   t2 = rn(t*t); t3 = rn(t2*t); t4 = rn(t2*t2)
//   cv = fmaf(p0,t4,0) -> fmaf(p1,t3,.) -> fmaf(p2,t2,.) -> fmaf(p3,t,.) -> +p4
//   ci = rintf(cv);  d = cv - ci (exact);  raw_pos = t - ci (exact integer)
//   gather weights {e^-16, e^-1, 1, e^-1, e^-16}, ascending-j partial sums;
//   interior path multiplies by constant reciprocal of the constant-folded
//   ascending weight sum (<=2 ulp; tolerance 1e-3). Edge path exact divides.
//
// Perf model (R12 post-mortem): kernel sits on the launch-overhead floor
// (T_ovh ~5000 cyc at idle DVFS clocks); per-thread chain ~600 cyc. Max
// wave-parallelism (128 CTAs over 148 SMs, single wave) beats per-thread
// ILP (R12: 32 CTAs ILP-4 regressed 4.83 -> 5.86 us). Gather LDGs are
// front-batched (MLP=6) so the second memory round-trip is paid once.

#ifndef SIG_LEN
#define SIG_LEN 2048
#endif

__global__ __launch_bounds__(256, 1)
void ParametricInterpolation_kernel(
    const float* __restrict__ x,       // [B, N]
    const float* __restrict__ params,  // [B, 5]
    float* __restrict__ out,           // [B, N]
    float* __restrict__ curve,         // [B, N] or nullptr
    int B)
{
    const int N = SIG_LEN;
    int gid = blockIdx.x * blockDim.x + threadIdx.x;
    if (gid >= B * N) return;
    int b = gid >> 11;
    int i = gid & (N - 1);

    // ---- rint-critical pipeline (PROTECTED) ----
    const float r0 = __fdiv_rn(1.0f, 1e11f);   // constant-folded rn(1/c)
    const float r1 = __fdiv_rn(1.0f, 1e7f);
    const float r2 = __fdiv_rn(1.0f, 1e3f);

    const float* pb = params + b * 5;
    float p0 = __fmul_rn(__ldg(pb + 0), r0);
    float p1 = __fmul_rn(__ldg(pb + 1), r1);
    float p2 = __fmul_rn(__ldg(pb + 2), r2);
    float p3 = __ldg(pb + 3);
    float p4 = __ldg(pb + 4);

    float t  = (float)i;
    float t2 = __fmul_rn(t, t);
    float t3 = __fmul_rn(t2, t);
    float t4 = __fmul_rn(t2, t2);

    float cv = fmaf(p0, t4, 0.0f);
    cv = fmaf(p1, t3, cv);
    cv = fmaf(p2, t2, cv);
    cv = fmaf(p3, t,  cv);
    cv = __fadd_rn(cv, p4);

    float ci = rintf(cv);
    float d  = __fadd_rn(cv, -ci);

    float raw_pos = __fadd_rn(t, -ci);          // exact integer
    float np_f = fminf(fmaxf(raw_pos, 1.0f), 2047.0f);
    int m = (int)np_f;

    // ---- constant-weight gather ----
    const float W1 = 0.36787944117144233f;      // f32(exp(-1))
    const float W2 = 1.1253517471925912e-07f;   // f32(exp(-16))
    const float WS = __fadd_rn(__fadd_rn(__fadd_rn(__fadd_rn(W2, W1), 1.0f), W1), W2);
    const float RW = __fdiv_rn(1.0f, WS);       // constant reciprocal

    const float* xr = x + b * N;
    float a1, a2;

    if (__builtin_expect(m >= 3 && m <= 2044, 1)) {
        // Interior (overwhelmingly common): front-batch all 6 LDGs so the
        // data-dependent round-trip latency is exposed exactly once (MLP=6).
        float xm3 = __ldg(xr + m - 3);
        float xm2 = __ldg(xr + m - 2);
        float xm1 = __ldg(xr + m - 1);
        float x0  = __ldg(xr + m);
        float xp1 = __ldg(xr + m + 1);
        float xp2 = __ldg(xr + m + 2);

        // s1: taps m-2..m+2, ascending j (reference partial-sum order)
        float s1 = __fmul_rn(xm2, W2);
        s1 = fmaf(xm1, W1, s1);
        s1 = __fadd_rn(s1, x0);
        s1 = fmaf(xp1, W1, s1);
        s1 = fmaf(xp2, W2, s1);
        // s2: taps m-3..m+1 (center m-1), ascending j
        float s2 = __fmul_rn(xm3, W2);
        s2 = fmaf(xm2, W1, s2);
        s2 = __fadd_rn(s2, xm1);
        s2 = fmaf(x0,  W1, s2);
        s2 = fmaf(xp1, W2, s2);

        a1 = __fmul_rn(s1, RW);
        a2 = __fmul_rn(s2, RW);
    } else {
        // Edge: bounds-checked taps, exact weight sums + IEEE divides.
        float s1 = 0.0f, w1s = 0.0f, s2 = 0.0f, w2s = 0.0f;
        #pragma unroll
        for (int o = -3; o <= 2; o++) {
            int j = m + o;
            if (j < 0 || j >= N) continue;
            float xv = __ldg(xr + j);
            float wk1 = (o == 0) ? 1.0f
                      : (o == -1 || o == 1) ? W1
                      : (o == -2 || o == 2) ? W2 : 0.0f;
            int o2 = o + 1;
            float wk2 = (o2 == 0) ? 1.0f
                      : (o2 == -1 || o2 == 1) ? W1
                      : (o2 == -2 || o2 == 2) ? W2 : 0.0f;
            s1  = fmaf(xv, wk1, s1);
            w1s = __fadd_rn(w1s, wk1);
            s2  = fmaf(xv, wk2, s2);
            w2s = __fadd_rn(w2s, wk2);
        }
        a1 = __fdiv_rn(s1, w1s);
        a2 = __fdiv_rn(s2, w2s);
    }

    // out = a1*(1-d) + a2*d
    float one_md = __fadd_rn(1.0f, -d);
    float o_val = __fadd_rn(__fmul_rn(a1, one_md), __fmul_rn(a2, d));

    out[gid] = o_val;
    if (curve) curve[gid] = cv;
}

extern "C" void kernel_launch(void* const* d_in, const int* in_sizes, int n_in,
                              void* d_out, int out_size)
{
    const float* x      = (const float*)d_in[0];   // [B, 2048] f32
    const float* params = (const float*)d_in[1];   // [B, 5]    f32
    float* out = (float*)d_out;

    int B = in_sizes[1] / 5;           // 16
    int total = B * SIG_LEN;           // 32768

    float* curve = (out_size >= 2 * total) ? (out + total) : nullptr;

    int threads = 256;
    int blocks = (total + threads - 1) / threads;  // 128
    ParametricInterpolation_kernel<<<blocks, threads>>>(x, params, out, curve, B);
}